// round 9
// baseline (speedup 1.0000x reference)
#include <cuda_runtime.h>
#include <math.h>

// SymmetricChannel — fused single-pass kernel, write-through store variant.
// Traffic = 896 MB algorithmic minimum. Reads streaming (__ldcs, evict-first);
// stores write-through (__stwt) so the L2 serves only the read streams and the
// write stream flows straight to the DRAM write queue.

static constexpr int V   = 2048;
static constexpr int VM1 = 2047;
static constexpr float PPROB    = 0.1f;
static constexpr float INV_VM2  = 1.0f / 2046.0f;
static constexpr float LOG_KEEP = -0.10536051565782628f;  // ln(0.9)
static constexpr float LOG_REP  = -9.9262269f;            // ln(0.1/2046)

__global__ __launch_bounds__(256)
void sym_channel_kernel(const float* __restrict__ msgs,
                        const float* __restrict__ logits,
                        const float* __restrict__ noise,
                        float* __restrict__ out,
                        int nrows)
{
    __shared__ float sm_tb[512];     // t of element (i4*4+3), one per float4 chunk
    __shared__ float warp_sums[8];

    const int r   = blockIdx.x;
    const int tid = threadIdx.x;
    const size_t rowoff = (size_t)r * V;
    const size_t N      = (size_t)nrows * V;

    const float4* m4   = reinterpret_cast<const float4*>(msgs + rowoff);
    const float4* l4   = reinterpret_cast<const float4*>(logits + rowoff);
    const float*  nrow = noise + (size_t)r * VM1;

    float4* out_m4  = reinterpret_cast<float4*>(out + rowoff);          // m_noisy
    float4* out_l4  = reinterpret_cast<float4*>(out + N + rowoff);      // logits_noisy
    float4* out_mc4 = reinterpret_cast<float4*>(out + 2 * N + rowoff);  // messages copy
    float4* out_lc4 = reinterpret_cast<float4*>(out + 3 * N + rowoff);  // logits copy

    // ---- front-batch all global loads, streaming (evict-first) policy ----
    float4 mv[2];
    mv[0] = __ldcs(&m4[tid]);
    mv[1] = __ldcs(&m4[tid + 256]);
    float4 lv[2];
    lv[0] = __ldcs(&l4[tid]);
    lv[1] = __ldcs(&l4[tid + 256]);
    const float l0 = __ldg(logits + rowoff);   // broadcast, 1 sector/row
    float nz[8];
    #pragma unroll
    for (int k = 0; k < 2; k++) {
        int base = (tid + k * 256) * 4;
        #pragma unroll
        for (int j = 0; j < 4; j++) {
            int c = base + j;
            nz[k * 4 + j] = (c < VM1) ? __ldcs(&nrow[c]) : 1.0f;  // >=P -> no hit
        }
    }

    // ---- verbatim copies (write-through stores) ----
    __stwt(&out_mc4[tid],       mv[0]);
    __stwt(&out_mc4[tid + 256], mv[1]);
    __stwt(&out_lc4[tid],       lv[0]);
    __stwt(&out_lc4[tid + 256], lv[1]);

    // ---- hit mask + local masked sum + boundary t to smem ----
    unsigned msk = 0;
    float lsum = 0.0f;
    #pragma unroll
    for (int k = 0; k < 2; k++) {
        const float* mp = &mv[k].x;
        #pragma unroll
        for (int j = 0; j < 4; j++) {
            if (nz[k * 4 + j] < PPROB) {
                msk |= 1u << (k * 4 + j);
                lsum += mp[j];
            }
        }
        sm_tb[tid + k * 256] = ((msk >> (k * 4 + 3)) & 1) ? mp[3] : 0.0f;
    }

    // ---- reduction arrive (barrier comes after the logits work below) ----
    float wsum = lsum;
    #pragma unroll
    for (int off = 16; off > 0; off >>= 1)
        wsum += __shfl_down_sync(0xFFFFFFFFu, wsum, off);
    if ((tid & 31) == 0) warp_sums[tid >> 5] = wsum;

    // ---- logits_noisy: independent of barrier/reduction, hides sync slack ----
    const float e0 = expf(l0);
    #pragma unroll
    for (int k = 0; k < 2; k++) {
        int i4 = tid + k * 256;
        const float* lp = &lv[k].x;
        float4 o;
        float* op = &o.x;
        #pragma unroll
        for (int j = 0; j < 4; j++) {
            int jj = i4 * 4 + j;
            if (jj == 0) { op[j] = l0; continue; }
            float ljv = lp[j];
            float pt = fminf(fmaxf(1.0f - expf(ljv) - e0, 0.0f), 1.0f);
            float a = ljv + LOG_KEEP;
            float b = logf(pt) + LOG_REP;        // logf(0) = -inf is fine
            float mx = fmaxf(a, b);
            float mn = fminf(a, b);
            op[j] = mx + log1pf(expf(mn - mx));  // exp(-inf)=0 -> mx
        }
        __stwt(&out_l4[i4], o);
    }

    __syncthreads();   // covers warp_sums + sm_tb

    float row_sum = 0.0f;
    #pragma unroll
    for (int w = 0; w < 8; w++) row_sum += warp_sums[w];
    const float add_c = row_sum * INV_VM2;
    const float scale = 1.0f + INV_VM2;

    // ---- m_noisy from registers; only j==0 touches smem ----
    #pragma unroll
    for (int k = 0; k < 2; k++) {
        int i4 = tid + k * 256;
        const float* mp = &mv[k].x;
        float4 o;
        float* op = &o.x;
        #pragma unroll
        for (int j = 0; j < 4; j++) {
            float tprev;
            if (j == 0) {
                tprev = (i4 == 0) ? 0.0f : sm_tb[i4 - 1];
            } else {
                tprev = ((msk >> (k * 4 + j - 1)) & 1) ? mp[j - 1] : 0.0f;
            }
            float val = mp[j];
            if (i4 * 4 + j > 0) val += add_c - tprev * scale;
            op[j] = val;
        }
        __stwt(&out_m4[i4], o);
    }
}

extern "C" void kernel_launch(void* const* d_in, const int* in_sizes, int n_in,
                              void* d_out, int out_size)
{
    const float* msgs   = (const float*)d_in[0];
    const float* logits = (const float*)d_in[1];
    const float* noise  = (const float*)d_in[2];
    float* out = (float*)d_out;
    int nrows = in_sizes[0] / V;   // 16384
    sym_channel_kernel<<<nrows, 256>>>(msgs, logits, noise, out, nrows);
}

// round 10
// speedup vs baseline: 1.0129x; 1.0129x over previous
#include <cuda_runtime.h>
#include <math.h>

// SymmetricChannel — fused single-pass kernel (FINAL, R3/R8 structure).
//
// Roofline: traffic = 896 MB, the algorithmic minimum (3 reads + 4 writes of
// [16384,2048] fp32). Sustains ~6.55 TB/s HBM (~82.6% DRAM busy), which nine
// rounds of structural probes (occupancy 48-96%, block 256/512, 1-8 rows/CTA
// incl. pipelined-persistent, fused vs split kernels, default/__stcs/__stwt
// cache policies) established as the practical HBM ceiling for this stream
// mix on GB300. __stcs > __stwt (L2 write-coalescing helps); streaming reads
// keep L2 ways free. One row per 256-thread CTA; single barrier; logits path
// scheduled before the barrier to hide reduction sync.

static constexpr int V   = 2048;
static constexpr int VM1 = 2047;
static constexpr float PPROB    = 0.1f;
static constexpr float INV_VM2  = 1.0f / 2046.0f;
static constexpr float LOG_KEEP = -0.10536051565782628f;  // ln(0.9)
static constexpr float LOG_REP  = -9.9262269f;            // ln(0.1/2046)

__global__ __launch_bounds__(256)
void sym_channel_kernel(const float* __restrict__ msgs,
                        const float* __restrict__ logits,
                        const float* __restrict__ noise,
                        float* __restrict__ out,
                        int nrows)
{
    __shared__ float sm_tb[512];     // t of element (i4*4+3), one per float4 chunk
    __shared__ float warp_sums[8];

    const int r   = blockIdx.x;
    const int tid = threadIdx.x;
    const size_t rowoff = (size_t)r * V;
    const size_t N      = (size_t)nrows * V;

    const float4* m4   = reinterpret_cast<const float4*>(msgs + rowoff);
    const float4* l4   = reinterpret_cast<const float4*>(logits + rowoff);
    const float*  nrow = noise + (size_t)r * VM1;

    float4* out_m4  = reinterpret_cast<float4*>(out + rowoff);          // m_noisy
    float4* out_l4  = reinterpret_cast<float4*>(out + N + rowoff);      // logits_noisy
    float4* out_mc4 = reinterpret_cast<float4*>(out + 2 * N + rowoff);  // messages copy
    float4* out_lc4 = reinterpret_cast<float4*>(out + 3 * N + rowoff);  // logits copy

    // ---- front-batch all global loads, streaming (evict-first) policy ----
    float4 mv[2];
    mv[0] = __ldcs(&m4[tid]);
    mv[1] = __ldcs(&m4[tid + 256]);
    float4 lv[2];
    lv[0] = __ldcs(&l4[tid]);
    lv[1] = __ldcs(&l4[tid + 256]);
    const float l0 = __ldg(logits + rowoff);   // broadcast, 1 sector/row
    float nz[8];
    #pragma unroll
    for (int k = 0; k < 2; k++) {
        int base = (tid + k * 256) * 4;
        #pragma unroll
        for (int j = 0; j < 4; j++) {
            int c = base + j;
            nz[k * 4 + j] = (c < VM1) ? __ldcs(&nrow[c]) : 1.0f;  // >=P -> no hit
        }
    }

    // ---- verbatim copies (streaming stores) ----
    __stcs(&out_mc4[tid],       mv[0]);
    __stcs(&out_mc4[tid + 256], mv[1]);
    __stcs(&out_lc4[tid],       lv[0]);
    __stcs(&out_lc4[tid + 256], lv[1]);

    // ---- hit mask + local masked sum + boundary t to smem ----
    unsigned msk = 0;
    float lsum = 0.0f;
    #pragma unroll
    for (int k = 0; k < 2; k++) {
        const float* mp = &mv[k].x;
        #pragma unroll
        for (int j = 0; j < 4; j++) {
            if (nz[k * 4 + j] < PPROB) {
                msk |= 1u << (k * 4 + j);
                lsum += mp[j];
            }
        }
        sm_tb[tid + k * 256] = ((msk >> (k * 4 + 3)) & 1) ? mp[3] : 0.0f;
    }

    // ---- reduction arrive (barrier comes after the logits work below) ----
    float wsum = lsum;
    #pragma unroll
    for (int off = 16; off > 0; off >>= 1)
        wsum += __shfl_down_sync(0xFFFFFFFFu, wsum, off);
    if ((tid & 31) == 0) warp_sums[tid >> 5] = wsum;

    // ---- logits_noisy: independent of barrier/reduction, hides sync slack ----
    const float e0 = expf(l0);
    #pragma unroll
    for (int k = 0; k < 2; k++) {
        int i4 = tid + k * 256;
        const float* lp = &lv[k].x;
        float4 o;
        float* op = &o.x;
        #pragma unroll
        for (int j = 0; j < 4; j++) {
            int jj = i4 * 4 + j;
            if (jj == 0) { op[j] = l0; continue; }
            float ljv = lp[j];
            float pt = fminf(fmaxf(1.0f - expf(ljv) - e0, 0.0f), 1.0f);
            float a = ljv + LOG_KEEP;
            float b = logf(pt) + LOG_REP;        // logf(0) = -inf is fine
            float mx = fmaxf(a, b);
            float mn = fminf(a, b);
            op[j] = mx + log1pf(expf(mn - mx));  // exp(-inf)=0 -> mx
        }
        __stcs(&out_l4[i4], o);
    }

    __syncthreads();   // covers warp_sums + sm_tb

    float row_sum = 0.0f;
    #pragma unroll
    for (int w = 0; w < 8; w++) row_sum += warp_sums[w];
    const float add_c = row_sum * INV_VM2;
    const float scale = 1.0f + INV_VM2;

    // ---- m_noisy from registers; only j==0 touches smem ----
    #pragma unroll
    for (int k = 0; k < 2; k++) {
        int i4 = tid + k * 256;
        const float* mp = &mv[k].x;
        float4 o;
        float* op = &o.x;
        #pragma unroll
        for (int j = 0; j < 4; j++) {
            float tprev;
            if (j == 0) {
                tprev = (i4 == 0) ? 0.0f : sm_tb[i4 - 1];
            } else {
                tprev = ((msk >> (k * 4 + j - 1)) & 1) ? mp[j - 1] : 0.0f;
            }
            float val = mp[j];
            if (i4 * 4 + j > 0) val += add_c - tprev * scale;
            op[j] = val;
        }
        __stcs(&out_m4[i4], o);
    }
}

extern "C" void kernel_launch(void* const* d_in, const int* in_sizes, int n_in,
                              void* d_out, int out_size)
{
    const float* msgs   = (const float*)d_in[0];
    const float* logits = (const float*)d_in[1];
    const float* noise  = (const float*)d_in[2];
    float* out = (float*)d_out;
    int nrows = in_sizes[0] / V;   // 16384
    sym_channel_kernel<<<nrows, 256>>>(msgs, logits, noise, out, nrows);
}

// round 11
// speedup vs baseline: 1.0159x; 1.0030x over previous
#include <cuda_runtime.h>
#include <math.h>

// SymmetricChannel — fused single-pass kernel (CONVERGED OPTIMUM).
//
// Traffic = algorithmic minimum (3 reads + 4 writes of [16384,2048] fp32,
// ~939 MB). Sustains ~6.53-6.57 TB/s HBM (~82.5% DRAM busy) — established
// over 10 rounds as the GB300 ceiling for this read/write mix:
//   occupancy 48-96%           -> neutral
//   block 256x2 / 512x1        -> neutral
//   2 rows/CTA, 8-row pipeline -> worse (reg pressure / spill)
//   split msgs/logits kernels  -> worse (serialization, no BW gain)
//   __stwt write-through       -> worse (L2 write-coalescing is useful)
//   __ldcs/__stcs streaming    -> best-or-equal
// Structure: one row per 256-thread CTA, front-batched loads, 2 KB smem,
// single barrier, logits path scheduled before the barrier.

static constexpr int V   = 2048;
static constexpr int VM1 = 2047;
static constexpr float PPROB    = 0.1f;
static constexpr float INV_VM2  = 1.0f / 2046.0f;
static constexpr float LOG_KEEP = -0.10536051565782628f;  // ln(0.9)
static constexpr float LOG_REP  = -9.9262269f;            // ln(0.1/2046)

__global__ __launch_bounds__(256)
void sym_channel_kernel(const float* __restrict__ msgs,
                        const float* __restrict__ logits,
                        const float* __restrict__ noise,
                        float* __restrict__ out,
                        int nrows)
{
    __shared__ float sm_tb[512];     // t of element (i4*4+3), one per float4 chunk
    __shared__ float warp_sums[8];

    const int r   = blockIdx.x;
    const int tid = threadIdx.x;
    const size_t rowoff = (size_t)r * V;
    const size_t N      = (size_t)nrows * V;

    const float4* m4   = reinterpret_cast<const float4*>(msgs + rowoff);
    const float4* l4   = reinterpret_cast<const float4*>(logits + rowoff);
    const float*  nrow = noise + (size_t)r * VM1;

    float4* out_m4  = reinterpret_cast<float4*>(out + rowoff);          // m_noisy
    float4* out_l4  = reinterpret_cast<float4*>(out + N + rowoff);      // logits_noisy
    float4* out_mc4 = reinterpret_cast<float4*>(out + 2 * N + rowoff);  // messages copy
    float4* out_lc4 = reinterpret_cast<float4*>(out + 3 * N + rowoff);  // logits copy

    // ---- front-batch all global loads, streaming (evict-first) policy ----
    float4 mv[2];
    mv[0] = __ldcs(&m4[tid]);
    mv[1] = __ldcs(&m4[tid + 256]);
    float4 lv[2];
    lv[0] = __ldcs(&l4[tid]);
    lv[1] = __ldcs(&l4[tid + 256]);
    const float l0 = __ldg(logits + rowoff);   // broadcast, 1 sector/row
    float nz[8];
    #pragma unroll
    for (int k = 0; k < 2; k++) {
        int base = (tid + k * 256) * 4;
        #pragma unroll
        for (int j = 0; j < 4; j++) {
            int c = base + j;
            nz[k * 4 + j] = (c < VM1) ? __ldcs(&nrow[c]) : 1.0f;  // >=P -> no hit
        }
    }

    // ---- verbatim copies (streaming stores) ----
    __stcs(&out_mc4[tid],       mv[0]);
    __stcs(&out_mc4[tid + 256], mv[1]);
    __stcs(&out_lc4[tid],       lv[0]);
    __stcs(&out_lc4[tid + 256], lv[1]);

    // ---- hit mask + local masked sum + boundary t to smem ----
    unsigned msk = 0;
    float lsum = 0.0f;
    #pragma unroll
    for (int k = 0; k < 2; k++) {
        const float* mp = &mv[k].x;
        #pragma unroll
        for (int j = 0; j < 4; j++) {
            if (nz[k * 4 + j] < PPROB) {
                msk |= 1u << (k * 4 + j);
                lsum += mp[j];
            }
        }
        sm_tb[tid + k * 256] = ((msk >> (k * 4 + 3)) & 1) ? mp[3] : 0.0f;
    }

    // ---- reduction arrive (barrier comes after the logits work below) ----
    float wsum = lsum;
    #pragma unroll
    for (int off = 16; off > 0; off >>= 1)
        wsum += __shfl_down_sync(0xFFFFFFFFu, wsum, off);
    if ((tid & 31) == 0) warp_sums[tid >> 5] = wsum;

    // ---- logits_noisy: independent of barrier/reduction, hides sync slack ----
    const float e0 = expf(l0);
    #pragma unroll
    for (int k = 0; k < 2; k++) {
        int i4 = tid + k * 256;
        const float* lp = &lv[k].x;
        float4 o;
        float* op = &o.x;
        #pragma unroll
        for (int j = 0; j < 4; j++) {
            int jj = i4 * 4 + j;
            if (jj == 0) { op[j] = l0; continue; }
            float ljv = lp[j];
            float pt = fminf(fmaxf(1.0f - expf(ljv) - e0, 0.0f), 1.0f);
            float a = ljv + LOG_KEEP;
            float b = logf(pt) + LOG_REP;        // logf(0) = -inf is fine
            float mx = fmaxf(a, b);
            float mn = fminf(a, b);
            op[j] = mx + log1pf(expf(mn - mx));  // exp(-inf)=0 -> mx
        }
        __stcs(&out_l4[i4], o);
    }

    __syncthreads();   // covers warp_sums + sm_tb

    float row_sum = 0.0f;
    #pragma unroll
    for (int w = 0; w < 8; w++) row_sum += warp_sums[w];
    const float add_c = row_sum * INV_VM2;
    const float scale = 1.0f + INV_VM2;

    // ---- m_noisy from registers; only j==0 touches smem ----
    #pragma unroll
    for (int k = 0; k < 2; k++) {
        int i4 = tid + k * 256;
        const float* mp = &mv[k].x;
        float4 o;
        float* op = &o.x;
        #pragma unroll
        for (int j = 0; j < 4; j++) {
            float tprev;
            if (j == 0) {
                tprev = (i4 == 0) ? 0.0f : sm_tb[i4 - 1];
            } else {
                tprev = ((msk >> (k * 4 + j - 1)) & 1) ? mp[j - 1] : 0.0f;
            }
            float val = mp[j];
            if (i4 * 4 + j > 0) val += add_c - tprev * scale;
            op[j] = val;
        }
        __stcs(&out_m4[i4], o);
    }
}

extern "C" void kernel_launch(void* const* d_in, const int* in_sizes, int n_in,
                              void* d_out, int out_size)
{
    const float* msgs   = (const float*)d_in[0];
    const float* logits = (const float*)d_in[1];
    const float* noise  = (const float*)d_in[2];
    float* out = (float*)d_out;
    int nrows = in_sizes[0] / V;   // 16384
    sym_channel_kernel<<<nrows, 256>>>(msgs, logits, noise, out, nrows);
}

// round 12
// speedup vs baseline: 1.0243x; 1.0082x over previous
#include <cuda_runtime.h>
#include <math.h>

// SymmetricChannel — fused single-pass kernel (CONVERGED OPTIMUM).
//
// Traffic = algorithmic minimum (3 reads + 4 writes of [16384,2048] fp32,
// ~896 MB). Sustains ~6.53-6.60 TB/s HBM (~82.5-83.3% DRAM busy) — the GB300
// ceiling for this read/write mix, established over 11 rounds:
//   occupancy 48-96%, block 256/512, 1-8 rows/CTA, pipelined-persistent,
//   fused vs split kernels, default/__ldcs+__stcs/__stwt -> all neutral or
//   worse except this configuration. CE-offloaded copies rejected by
//   arithmetic (would re-read inputs: 896 -> 1152 MB).
// Structure: one row per 256-thread CTA, noise+messages loads issued first
// (reduction critical path), 2 KB smem, single barrier, logits path
// scheduled before the barrier to hide reduction sync.

static constexpr int V   = 2048;
static constexpr int VM1 = 2047;
static constexpr float PPROB    = 0.1f;
static constexpr float INV_VM2  = 1.0f / 2046.0f;
static constexpr float LOG_KEEP = -0.10536051565782628f;  // ln(0.9)
static constexpr float LOG_REP  = -9.9262269f;            // ln(0.1/2046)

__global__ __launch_bounds__(256)
void sym_channel_kernel(const float* __restrict__ msgs,
                        const float* __restrict__ logits,
                        const float* __restrict__ noise,
                        float* __restrict__ out,
                        int nrows)
{
    __shared__ float sm_tb[512];     // t of element (i4*4+3), one per float4 chunk
    __shared__ float warp_sums[8];

    const int r   = blockIdx.x;
    const int tid = threadIdx.x;
    const size_t rowoff = (size_t)r * V;
    const size_t N      = (size_t)nrows * V;

    const float4* m4   = reinterpret_cast<const float4*>(msgs + rowoff);
    const float4* l4   = reinterpret_cast<const float4*>(logits + rowoff);
    const float*  nrow = noise + (size_t)r * VM1;

    float4* out_m4  = reinterpret_cast<float4*>(out + rowoff);          // m_noisy
    float4* out_l4  = reinterpret_cast<float4*>(out + N + rowoff);      // logits_noisy
    float4* out_mc4 = reinterpret_cast<float4*>(out + 2 * N + rowoff);  // messages copy
    float4* out_lc4 = reinterpret_cast<float4*>(out + 3 * N + rowoff);  // logits copy

    // ---- front-batch loads; reduction-critical (msgs, noise) issued first ----
    float4 mv[2];
    mv[0] = __ldcs(&m4[tid]);
    mv[1] = __ldcs(&m4[tid + 256]);
    float nz[8];
    #pragma unroll
    for (int k = 0; k < 2; k++) {
        int base = (tid + k * 256) * 4;
        #pragma unroll
        for (int j = 0; j < 4; j++) {
            int c = base + j;
            nz[k * 4 + j] = (c < VM1) ? __ldcs(&nrow[c]) : 1.0f;  // >=P -> no hit
        }
    }
    float4 lv[2];
    lv[0] = __ldcs(&l4[tid]);
    lv[1] = __ldcs(&l4[tid + 256]);
    const float l0 = __ldg(logits + rowoff);   // broadcast, 1 sector/row

    // ---- hit mask + local masked sum + boundary t to smem (critical path) ----
    unsigned msk = 0;
    float lsum = 0.0f;
    #pragma unroll
    for (int k = 0; k < 2; k++) {
        const float* mp = &mv[k].x;
        #pragma unroll
        for (int j = 0; j < 4; j++) {
            if (nz[k * 4 + j] < PPROB) {
                msk |= 1u << (k * 4 + j);
                lsum += mp[j];
            }
        }
        sm_tb[tid + k * 256] = ((msk >> (k * 4 + 3)) & 1) ? mp[3] : 0.0f;
    }

    // ---- reduction arrive (barrier comes after the stores/logits below) ----
    float wsum = lsum;
    #pragma unroll
    for (int off = 16; off > 0; off >>= 1)
        wsum += __shfl_down_sync(0xFFFFFFFFu, wsum, off);
    if ((tid & 31) == 0) warp_sums[tid >> 5] = wsum;

    // ---- verbatim copies (streaming stores) ----
    __stcs(&out_mc4[tid],       mv[0]);
    __stcs(&out_mc4[tid + 256], mv[1]);
    __stcs(&out_lc4[tid],       lv[0]);
    __stcs(&out_lc4[tid + 256], lv[1]);

    // ---- logits_noisy: independent of barrier/reduction, hides sync slack ----
    const float e0 = expf(l0);
    #pragma unroll
    for (int k = 0; k < 2; k++) {
        int i4 = tid + k * 256;
        const float* lp = &lv[k].x;
        float4 o;
        float* op = &o.x;
        #pragma unroll
        for (int j = 0; j < 4; j++) {
            int jj = i4 * 4 + j;
            if (jj == 0) { op[j] = l0; continue; }
            float ljv = lp[j];
            float pt = fminf(fmaxf(1.0f - expf(ljv) - e0, 0.0f), 1.0f);
            float a = ljv + LOG_KEEP;
            float b = logf(pt) + LOG_REP;        // logf(0) = -inf is fine
            float mx = fmaxf(a, b);
            float mn = fminf(a, b);
            op[j] = mx + log1pf(expf(mn - mx));  // exp(-inf)=0 -> mx
        }
        __stcs(&out_l4[i4], o);
    }

    __syncthreads();   // covers warp_sums + sm_tb

    float row_sum = 0.0f;
    #pragma unroll
    for (int w = 0; w < 8; w++) row_sum += warp_sums[w];
    const float add_c = row_sum * INV_VM2;
    const float scale = 1.0f + INV_VM2;

    // ---- m_noisy from registers; only j==0 touches smem ----
    #pragma unroll
    for (int k = 0; k < 2; k++) {
        int i4 = tid + k * 256;
        const float* mp = &mv[k].x;
        float4 o;
        float* op = &o.x;
        #pragma unroll
        for (int j = 0; j < 4; j++) {
            float tprev;
            if (j == 0) {
                tprev = (i4 == 0) ? 0.0f : sm_tb[i4 - 1];
            } else {
                tprev = ((msk >> (k * 4 + j - 1)) & 1) ? mp[j - 1] : 0.0f;
            }
            float val = mp[j];
            if (i4 * 4 + j > 0) val += add_c - tprev * scale;
            op[j] = val;
        }
        __stcs(&out_m4[i4], o);
    }
}

extern "C" void kernel_launch(void* const* d_in, const int* in_sizes, int n_in,
                              void* d_out, int out_size)
{
    const float* msgs   = (const float*)d_in[0];
    const float* logits = (const float*)d_in[1];
    const float* noise  = (const float*)d_in[2];
    float* out = (float*)d_out;
    int nrows = in_sizes[0] / V;   // 16384
    sym_channel_kernel<<<nrows, 256>>>(msgs, logits, noise, out, nrows);
}